// round 1
// baseline (speedup 1.0000x reference)
#include <cuda_runtime.h>
#include <cuda_bf16.h>

#define NPTS 1048576
#define KNEI 16

// Scratch: padded points (float4-aligned -> each random gather = exactly one
// 32B sector in L2) and a double accumulator.
__device__ float4 g_pts4[NPTS];
__device__ double g_acc;

// Kernel 1: pad [N,3] f32 -> [N] float4 and zero the accumulator.
__global__ void pad_points_kernel(const float* __restrict__ pts) {
    int i = blockIdx.x * blockDim.x + threadIdx.x;
    if (i == 0) g_acc = 0.0;
    if (i < NPTS) {
        // Warp reads 384B contiguous -> fully coalesced despite stride-3.
        float x = pts[3 * i + 0];
        float y = pts[3 * i + 1];
        float z = pts[3 * i + 2];
        g_pts4[i] = make_float4(x, y, z, 0.0f);
    }
}

// Kernel 2: one thread per source point n; 16 neighbours each.
__global__ void __launch_bounds__(256) neighbour_loss_kernel(
    const int* __restrict__ idx,
    const float* __restrict__ orig)
{
    int n = blockIdx.x * blockDim.x + threadIdx.x;

    float tsum = 0.0f;
    if (n < NPTS) {
        float4 p = g_pts4[n];

        // Vectorized, fully coalesced loads of this thread's 16 indices and
        // 16 original distances (4 x int4 / 4 x float4).
        const int4*   idx4  = reinterpret_cast<const int4*>(idx)   + n * 4;
        const float4* orig4 = reinterpret_cast<const float4*>(orig) + n * 4;

        int   j[KNEI];
        float o[KNEI];
        #pragma unroll
        for (int v = 0; v < 4; ++v) {
            int4   iv = idx4[v];
            float4 ov = orig4[v];
            j[4*v+0] = iv.x; j[4*v+1] = iv.y; j[4*v+2] = iv.z; j[4*v+3] = iv.w;
            o[4*v+0] = ov.x; o[4*v+1] = ov.y; o[4*v+2] = ov.z; o[4*v+3] = ov.w;
        }

        // 16 independent LDG.128 gathers -> high MLP, each exactly 1 sector.
        float4 q[KNEI];
        #pragma unroll
        for (int k = 0; k < KNEI; ++k) q[k] = __ldg(&g_pts4[j[k]]);

        #pragma unroll
        for (int k = 0; k < KNEI; ++k) {
            float dx = p.x - q[k].x;
            float dy = p.y - q[k].y;
            float dz = p.z - q[k].z;
            float curr = fmaf(dx, dx, fmaf(dy, dy, dz * dz));
            float e = curr - o[k];
            tsum = fmaf(e, e, tsum);
        }
    }

    // Warp reduce
    #pragma unroll
    for (int off = 16; off > 0; off >>= 1)
        tsum += __shfl_down_sync(0xFFFFFFFFu, tsum, off);

    // Block reduce via shared
    __shared__ float warp_sums[8];
    int lane = threadIdx.x & 31;
    int wid  = threadIdx.x >> 5;
    if (lane == 0) warp_sums[wid] = tsum;
    __syncthreads();
    if (wid == 0) {
        float bs = (lane < 8) ? warp_sums[lane] : 0.0f;
        #pragma unroll
        for (int off = 4; off > 0; off >>= 1)
            bs += __shfl_down_sync(0xFFFFFFFFu, bs, off);
        if (lane == 0) atomicAdd(&g_acc, (double)bs);
    }
}

// Kernel 3: finalize scalar output.
__global__ void finalize_kernel(float* __restrict__ out) {
    out[0] = (float)(g_acc / 16777216.0 * 100000.0);
}

extern "C" void kernel_launch(void* const* d_in, const int* in_sizes, int n_in,
                              void* d_out, int out_size) {
    const float* points = (const float*)d_in[0];
    const int*   nidx   = (const int*)d_in[1];
    const float* orig   = (const float*)d_in[2];
    float* out = (float*)d_out;

    (void)in_sizes; (void)n_in; (void)out_size;

    const int threads = 256;
    pad_points_kernel<<<(NPTS + threads - 1) / threads, threads>>>(points);
    neighbour_loss_kernel<<<(NPTS + threads - 1) / threads, threads>>>(nidx, orig);
    finalize_kernel<<<1, 1>>>(out);
}